// round 15
// baseline (speedup 1.0000x reference)
#include <cuda_runtime.h>
#include <cuda_fp16.h>
#include <math.h>
#include <stdint.h>

// ---------------------------------------------------------------------------
// EBP_binaryNet forward with mma.sync (HMMA) GEMMs (plain sm_100 PTX).
// R15 = R14 + gemm2/3 fused A-side BN+tanh+split loader (MODE 1, k32 chunks,
// occupancy-2 preserved, mu/rs in DYNAMIC smem). split_act kernels and
// g_ah/g_al removed; h ping-pongs g_hA <-> g_hB.
// ---------------------------------------------------------------------------

#define M_ROWS 65536
#define IN_DIM 784
#define K1PAD  832            // storage stride: 13 * 64
#define H_DIM  512
#define D_OUT  10
#define SQ2PI  0.79788456f
#define BN_EPS 1e-5f

// gemm1 (MODE 0): k64 chunks
#define STAGE1 49152          // Ah0|Ah1 16K | Al0|Al1 16K | Bh0|Bh1 16K
#define SMEM_G1 (STAGE1 * 2)  // 96 KB
// gemm2/3 (MODE 1): k32 chunks
#define STAGE2 24576          // Ah 8K | Al 8K | Bh 8K
#define SMEM_G2 (STAGE2 * 2 + 4096)   // 52 KB (incl mu/rs tail)

// ------------------------- device scratch ----------------------------------
__device__ __align__(128) __half g_xh[(size_t)M_ROWS * K1PAD];
__device__ __align__(128) __half g_xl[(size_t)M_ROWS * K1PAD];
__device__ __align__(128) float  g_hA[(size_t)M_ROWS * H_DIM];
__device__ __align__(128) float  g_hB[(size_t)M_ROWS * H_DIM];
__device__ __align__(128) __half g_w0h[H_DIM * K1PAD];   // [n][k]
__device__ __align__(128) __half g_w1h[H_DIM * H_DIM];
__device__ __align__(128) __half g_w3h[H_DIM * H_DIM];
__device__ float g_mlast[H_DIM * D_OUT];
__device__ float g_scale[3][H_DIM];
__device__ float g_sum[3][H_DIM];
__device__ float g_sumsq[3][H_DIM];
__device__ float g_loss[1];
__device__ int   g_correct[1];

// ------------------------- PTX helpers -------------------------------------
__device__ __forceinline__ uint32_t s2u(const void* p) {
    uint32_t a;
    asm("{ .reg .u64 t; cvta.to.shared.u64 t, %1; cvt.u32.u64 %0, t; }" : "=r"(a) : "l"(p));
    return a;
}
__device__ __forceinline__ void cp16(uint32_t s, const void* g) {
    asm volatile("cp.async.cg.shared.global [%0], [%1], 16;" :: "r"(s), "l"(g));
}
#define CP_COMMIT() asm volatile("cp.async.commit_group;" ::: "memory")
#define CP_WAIT(n)  asm volatile("cp.async.wait_group %0;" :: "n"(n) : "memory")

__device__ __forceinline__ void ldsm4(uint32_t a, uint32_t* r) {
    asm volatile("ldmatrix.sync.aligned.m8n8.x4.shared.b16 {%0,%1,%2,%3}, [%4];"
                 : "=r"(r[0]), "=r"(r[1]), "=r"(r[2]), "=r"(r[3]) : "r"(a));
}
__device__ __forceinline__ void mma16816(float* d, const uint32_t* a, const uint32_t* b) {
    asm volatile(
        "mma.sync.aligned.m16n8k16.row.col.f32.f16.f16.f32 "
        "{%0,%1,%2,%3},{%4,%5,%6,%7},{%8,%9},{%0,%1,%2,%3};"
        : "+f"(d[0]), "+f"(d[1]), "+f"(d[2]), "+f"(d[3])
        : "r"(a[0]), "r"(a[1]), "r"(a[2]), "r"(a[3]), "r"(b[0]), "r"(b[1]));
}
__device__ __forceinline__ void sts128(uint32_t addr, uint4 v) {
    asm volatile("st.shared.v4.b32 [%0], {%1,%2,%3,%4};"
                 :: "r"(addr), "r"(v.x), "r"(v.y), "r"(v.z), "r"(v.w) : "memory");
}

// swizzled byte offset of (row, 16B-unit) inside a Nx32-half sub-tile (64B rows)
__device__ __forceinline__ uint32_t swoff(int r, int u) {
    return (uint32_t)(r * 64 + ((u ^ ((r >> 1) & 3)) * 16));
}
__device__ __forceinline__ void split2(float v, __half& hi, __half& lo) {
    hi = __float2half(v);
    lo = __float2half(v - __half2float(hi));
}
__device__ __forceinline__ uint32_t pkh(__half a, __half b) {
    __half2 t = __halves2half2(a, b);
    return *reinterpret_cast<uint32_t*>(&t);
}

// ------------------------- prep kernels ------------------------------------
__global__ void k_prep_w0(const float* __restrict__ w0) {
    int n = blockIdx.x;
    for (int k = threadIdx.x; k < 800; k += 256) {
        float m = (k < IN_DIM) ? tanhf(0.5f * w0[k * H_DIM + n]) : 0.0f;
        g_w0h[n * K1PAD + k] = __float2half(m);
    }
}
__global__ void k_prep_misc(const float* __restrict__ w0, const float* __restrict__ wlast) {
    int i = blockIdx.x * blockDim.x + threadIdx.x;
    if (i < 3 * H_DIM) { (&g_sum[0][0])[i] = 0.0f; (&g_sumsq[0][0])[i] = 0.0f; }
    if (i == 0) { g_loss[0] = 0.0f; g_correct[0] = 0; }
    if (i < H_DIM * D_OUT) g_mlast[i] = tanhf(0.5f * wlast[i]);
    if (i < H_DIM) {
        float s = 0.0f;
        for (int k = 0; k < IN_DIM; k++) {
            float v = tanhf(0.5f * w0[k * H_DIM + i]);
            s += 1.0f - v * v;
        }
        g_scale[0][i] = SQ2PI * rsqrtf(s);
    }
}
__global__ void k_prep_w13(const float* __restrict__ w1, const float* __restrict__ w3) {
    int n = blockIdx.x;
    for (int k = threadIdx.x; k < H_DIM; k += 256) {
        g_w1h[n * H_DIM + k] = __float2half(tanhf(0.5f * w1[k * H_DIM + n]));
        g_w3h[n * H_DIM + k] = __float2half(tanhf(0.5f * w3[k * H_DIM + n]));
    }
}
__global__ void k_diag_rows(const float* __restrict__ w1, const float* __restrict__ w3) {
    int gb = blockIdx.x;
    const float* w = (gb < 64) ? w1 : w3;
    const int L = (gb < 64) ? 1 : 2;
    int row = ((gb & 63) * 256 + threadIdx.x) >> 5;
    int lane = threadIdx.x & 31;
    if (row >= H_DIM) return;
    float s = 0.0f;
    #pragma unroll
    for (int t = 0; t < H_DIM / 32; t++) {
        float v = tanhf(0.5f * w[row * H_DIM + t * 32 + lane]);
        s += 1.0f - v * v;
    }
    #pragma unroll
    for (int o = 16; o; o >>= 1) s += __shfl_xor_sync(0xFFFFFFFFu, s, o);
    if (lane == 0) g_scale[L][row] = SQ2PI * rsqrtf(s);
}
// x split: grid-strided float4 over real data; zero only cols [784, 800)
__global__ void __launch_bounds__(256) k_split_x(const float* __restrict__ x) {
    const int tid = blockIdx.x * 256 + threadIdx.x;
    const int nreal = M_ROWS * (IN_DIM / 4);
    const float4* xv = reinterpret_cast<const float4*>(x);
    uint2* oh = reinterpret_cast<uint2*>(g_xh);
    uint2* ol = reinterpret_cast<uint2*>(g_xl);
    for (int idx = tid; idx < nreal; idx += gridDim.x * 256) {
        const int row = idx / (IN_DIM / 4);
        const int c4  = idx - row * (IN_DIM / 4);
        float4 v = xv[idx];
        __half h0, l0, h1, l1, h2, l2, h3, l3;
        split2(v.x, h0, l0); split2(v.y, h1, l1);
        split2(v.z, h2, l2); split2(v.w, h3, l3);
        const int o = row * (K1PAD / 4) + c4;
        oh[o] = make_uint2(pkh(h0, h1), pkh(h2, h3));
        ol[o] = make_uint2(pkh(l0, l1), pkh(l2, l3));
    }
    const int npad = M_ROWS * 4;
    for (int idx = tid; idx < npad; idx += gridDim.x * 256) {
        const int row = idx >> 2;
        const int c4  = idx & 3;
        const int o = row * (K1PAD / 4) + (IN_DIM / 4) + c4;
        oh[o] = make_uint2(0u, 0u);
        ol[o] = make_uint2(0u, 0u);
    }
}

// ------------------------- shared GEMM pieces ------------------------------
struct FragCtx {
    uint32_t a_off[2][2], b_off[4][2];
    int wm, wn, lane;
};
__device__ __forceinline__ void frag_init(FragCtx& c, int tid) {
    c.lane = tid & 31;
    const int wid = tid >> 5;
    c.wm = wid >> 1; c.wn = wid & 1;
    const int ar = c.wm * 32 + (c.lane & 7) + ((c.lane >> 3) & 1) * 8;
    const int au = c.lane >> 4;
    const int br = c.wn * 64 + (c.lane & 7) + (c.lane >> 4) * 8;
    const int bu = (c.lane >> 3) & 1;
    #pragma unroll
    for (int mt = 0; mt < 2; mt++)
        #pragma unroll
        for (int ks = 0; ks < 2; ks++) c.a_off[mt][ks] = swoff(ar + mt * 16, au + 2 * ks);
    #pragma unroll
    for (int nb = 0; nb < 4; nb++)
        #pragma unroll
        for (int ks = 0; ks < 2; ks++) c.b_off[nb][ks] = swoff(br + nb * 16, bu + 2 * ks);
}
// compute one 32-col sub-tile: sa = A-hi base, sa+ALOF = A-lo, sbb = B base
template <int ALOF>
__device__ __forceinline__ void compute_sub(const FragCtx& c, uint32_t sa, uint32_t sbb,
                                            float (*acc)[8][4]) {
    #pragma unroll
    for (int ks = 0; ks < 2; ks++) {
        uint32_t ah[2][4], al[2][4];
        ldsm4(sa + c.a_off[0][ks], ah[0]);
        ldsm4(sa + c.a_off[1][ks], ah[1]);
        ldsm4(sa + ALOF + c.a_off[0][ks], al[0]);
        ldsm4(sa + ALOF + c.a_off[1][ks], al[1]);
        #pragma unroll
        for (int nb = 0; nb < 4; nb++) {
            uint32_t bh[4];
            ldsm4(sbb + c.b_off[nb][ks], bh);
            mma16816(acc[0][2 * nb],     ah[0], bh);
            mma16816(acc[1][2 * nb],     ah[1], bh);
            mma16816(acc[0][2 * nb + 1], ah[0], bh + 2);
            mma16816(acc[1][2 * nb + 1], ah[1], bh + 2);
            mma16816(acc[0][2 * nb],     al[0], bh);
            mma16816(acc[1][2 * nb],     al[1], bh);
            mma16816(acc[0][2 * nb + 1], al[0], bh + 2);
            mma16816(acc[1][2 * nb + 1], al[1], bh + 2);
        }
    }
}
// epilogue: (acc+bias)*scale -> C, fused column stats -> g_sum/g_sumsq[LOUT]
template <int LOUT>
__device__ __forceinline__ void gemm_epilogue(const FragCtx& c, char* smem,
    float (*acc)[8][4], int rowA0, int colB0,
    const float* __restrict__ bias, const float* __restrict__ scale,
    float* __restrict__ C, int tid)
{
    __syncthreads();
    float* s_sum = reinterpret_cast<float*>(smem);
    float* s_sq  = s_sum + 128;
    if (tid < 256) reinterpret_cast<float*>(smem)[tid] = 0.0f;
    __syncthreads();

    #pragma unroll
    for (int nt = 0; nt < 8; nt++) {
        const int cl = c.wn * 64 + nt * 8 + 2 * (c.lane & 3);
        const int col = colB0 + cl;
        const float b0 = __ldg(bias + col),     sc0 = __ldg(scale + col);
        const float b1 = __ldg(bias + col + 1), sc1 = __ldg(scale + col + 1);
        float cs0 = 0.f, cq0 = 0.f, cs1 = 0.f, cq1 = 0.f;
        #pragma unroll
        for (int mt = 0; mt < 2; mt++) {
            const int row0 = rowA0 + c.wm * 32 + mt * 16 + (c.lane >> 2);
            float2 o0, o1;
            o0.x = (acc[mt][nt][0] + b0) * sc0;
            o0.y = (acc[mt][nt][1] + b1) * sc1;
            o1.x = (acc[mt][nt][2] + b0) * sc0;
            o1.y = (acc[mt][nt][3] + b1) * sc1;
            *reinterpret_cast<float2*>(C + (size_t)row0 * H_DIM + col)       = o0;
            *reinterpret_cast<float2*>(C + (size_t)(row0 + 8) * H_DIM + col) = o1;
            cs0 += o0.x + o1.x;  cq0 += o0.x * o0.x + o1.x * o1.x;
            cs1 += o0.y + o1.y;  cq1 += o0.y * o0.y + o1.y * o1.y;
        }
        #pragma unroll
        for (int off = 4; off <= 16; off <<= 1) {
            cs0 += __shfl_xor_sync(0xFFFFFFFFu, cs0, off);
            cq0 += __shfl_xor_sync(0xFFFFFFFFu, cq0, off);
            cs1 += __shfl_xor_sync(0xFFFFFFFFu, cs1, off);
            cq1 += __shfl_xor_sync(0xFFFFFFFFu, cq1, off);
        }
        if ((c.lane >> 2) == 0) {
            atomicAdd(&s_sum[cl], cs0);     atomicAdd(&s_sq[cl], cq0);
            atomicAdd(&s_sum[cl + 1], cs1); atomicAdd(&s_sq[cl + 1], cq1);
        }
    }
    __syncthreads();
    if (tid < 128) {
        atomicAdd(&g_sum[LOUT][colB0 + tid], s_sum[tid]);
        atomicAdd(&g_sumsq[LOUT][colB0 + tid], s_sq[tid]);
    }
}

// ---------------- gemm1: half-split A (MODE 0), k64 chunks, tail -----------
__global__ void __launch_bounds__(256, 2) k_gemm1(const float* __restrict__ th0) {
    constexpr int K = K1PAD, NK = 13;
    extern __shared__ __align__(128) char smem[];
    const uint32_t sbase = s2u(smem);
    const int tid = threadIdx.x;
    const int rowA0 = blockIdx.y * 128, colB0 = blockIdx.x * 128;
    FragCtx c; frag_init(c, tid);

    const int r  = tid >> 1;
    const int hs = tid & 1;
    const __half* pAh = g_xh + (size_t)(rowA0 + r) * K + hs * 16;
    const __half* pAl = g_xl + (size_t)(rowA0 + r) * K + hs * 16;
    const __half* pBh = g_w0h + (size_t)(colB0 + r) * K + hs * 16;
    const uint32_t so0 = swoff(r, hs * 2);
    const uint32_t so1 = swoff(r, hs * 2 + 1);

    float acc[2][8][4] = {};

    auto issue = [&](int ch) {
        const uint32_t sb = sbase + (ch & 1) * STAGE1;
        const int nsub = (ch == NK - 1) ? 1 : 2;
        for (int sub = 0; sub < nsub; sub++) {
            const size_t kk = (size_t)ch * 64 + sub * 32;
            const uint32_t st = sb + sub * 8192;
            cp16(st +         so0, pAh + kk);  cp16(st +         so1, pAh + kk + 8);
            cp16(st + 16384 + so0, pAl + kk);  cp16(st + 16384 + so1, pAl + kk + 8);
            cp16(st + 32768 + so0, pBh + kk);  cp16(st + 32768 + so1, pBh + kk + 8);
        }
    };

    issue(0); CP_COMMIT();
    for (int ch = 0; ch < NK; ch++) {
        CP_WAIT(0);
        __syncthreads();
        if (ch + 1 < NK) { issue(ch + 1); CP_COMMIT(); }
        const uint32_t sbc = sbase + (ch & 1) * STAGE1;
        if (ch == NK - 1) {
            // tail: 16 real cols -> sub0/ks0 only
            uint32_t ah[2][4], al[2][4], bh[4];
            ldsm4(sbc + c.a_off[0][0], ah[0]);
            ldsm4(sbc + c.a_off[1][0], ah[1]);
            ldsm4(sbc + 16384 + c.a_off[0][0], al[0]);
            ldsm4(sbc + 16384 + c.a_off[1][0], al[1]);
            #pragma unroll
            for (int nb = 0; nb < 4; nb++) {
                ldsm4(sbc + 32768 + c.b_off[nb][0], bh);
                mma16816(acc[0][2 * nb],     ah[0], bh);
                mma16816(acc[1][2 * nb],     ah[1], bh);
                mma16816(acc[0][2 * nb + 1], ah[0], bh + 2);
                mma16816(acc[1][2 * nb + 1], ah[1], bh + 2);
                mma16816(acc[0][2 * nb],     al[0], bh);
                mma16816(acc[1][2 * nb],     al[1], bh);
                mma16816(acc[0][2 * nb + 1], al[0], bh + 2);
                mma16816(acc[1][2 * nb + 1], al[1], bh + 2);
            }
        } else {
            #pragma unroll
            for (int sub = 0; sub < 2; sub++)
                compute_sub<16384>(c, sbc + sub * 8192, sbc + 32768 + sub * 8192, acc);
        }
    }
    gemm_epilogue<0>(c, smem, acc, rowA0, colB0, th0, g_scale[0], g_hA, tid);
}

// -------- gemm2/3: fused BN+tanh+split A loader (MODE 1), k32 chunks -------
// A = tanh((Hin - mu[LIN]) * rstd[LIN]) computed in the load path; mu/rstd
// finalized in-prologue from g_sum/g_sumsq[LIN] into DYNAMIC smem tail.
template <int LIN, int LOUT>
__device__ __forceinline__ void gemm_fused(
    const float* __restrict__ Hin, const __half* __restrict__ Bh,
    const float* __restrict__ bias, const float* __restrict__ scale,
    float* __restrict__ C)
{
    constexpr int NK = 16;
    extern __shared__ __align__(128) char smem[];
    const uint32_t sbase = s2u(smem);
    float* s_mu = reinterpret_cast<float*>(smem + 2 * STAGE2);
    float* s_rs = s_mu + H_DIM;
    const int tid = threadIdx.x;
    const int rowA0 = blockIdx.y * 128, colB0 = blockIdx.x * 128;
    FragCtx c; frag_init(c, tid);

    // finalize BN stats into dynamic smem
    {
        const float inv = 1.0f / (float)M_ROWS;
        for (int i = tid; i < H_DIM; i += 256) {
            float mu = g_sum[LIN][i] * inv;
            float var = g_sumsq[LIN][i] * inv - mu * mu;
            s_mu[i] = mu;
            s_rs[i] = rsqrtf(var + BN_EPS);
        }
    }

    const int r  = tid >> 1;
    const int hs = tid & 1;
    const float*  pA  = Hin + (size_t)(rowA0 + r) * H_DIM + hs * 16;
    const __half* pBh = Bh + (size_t)(colB0 + r) * H_DIM + hs * 16;
    const uint32_t so0 = swoff(r, hs * 2);
    const uint32_t so1 = swoff(r, hs * 2 + 1);

    float acc[2][8][4] = {};
    float4 va[4];

    auto ldA = [&](int ch) {
        const float4* p = reinterpret_cast<const float4*>(pA + ch * 32);
        va[0] = p[0]; va[1] = p[1]; va[2] = p[2]; va[3] = p[3];
    };
    auto issueB = [&](int ch) {
        const uint32_t sb = sbase + (ch & 1) * STAGE2;
        cp16(sb + 16384 + so0, pBh + ch * 32);
        cp16(sb + 16384 + so1, pBh + ch * 32 + 8);
    };
    auto stA = [&](int ch) {
        const uint32_t sb = sbase + (ch & 1) * STAGE2;
        const int kb = ch * 32 + hs * 16;
        float f[16];
        #pragma unroll
        for (int j = 0; j < 4; j++) {
            f[4*j+0] = va[j].x; f[4*j+1] = va[j].y; f[4*j+2] = va[j].z; f[4*j+3] = va[j].w;
        }
        #pragma unroll
        for (int i = 0; i < 16; i++) f[i] = tanhf((f[i] - s_mu[kb + i]) * s_rs[kb + i]);
        __half hh[16], ll[16];
        #pragma unroll
        for (int i = 0; i < 16; i++) split2(f[i], hh[i], ll[i]);
        uint4 hu0 = make_uint4(pkh(hh[0],hh[1]),  pkh(hh[2],hh[3]),  pkh(hh[4],hh[5]),  pkh(hh[6],hh[7]));
        uint4 hu1 = make_uint4(pkh(hh[8],hh[9]),  pkh(hh[10],hh[11]),pkh(hh[12],hh[13]),pkh(hh[14],hh[15]));
        uint4 lu0 = make_uint4(pkh(ll[0],ll[1]),  pkh(ll[2],ll[3]),  pkh(ll[4],ll[5]),  pkh(ll[6],ll[7]));
        uint4 lu1 = make_uint4(pkh(ll[8],ll[9]),  pkh(ll[10],ll[11]),pkh(ll[12],ll[13]),pkh(ll[14],ll[15]));
        sts128(sb +        so0, hu0); sts128(sb +        so1, hu1);
        sts128(sb + 8192 + so0, lu0); sts128(sb + 8192 + so1, lu1);
    };

    // prologue
    ldA(0);
    issueB(0); CP_COMMIT();
    __syncthreads();           // s_mu/s_rs visible before stA
    stA(0);

    for (int ch = 0; ch < NK; ch++) {
        CP_WAIT(0);
        __syncthreads();       // B(ch)+A(ch) staged everywhere; compute(ch-1) done
        if (ch + 1 < NK) { ldA(ch + 1); issueB(ch + 1); CP_COMMIT(); }
        const uint32_t sb = sbase + (ch & 1) * STAGE2;
        compute_sub<8192>(c, sb, sb + 16384, acc);
        if (ch + 1 < NK) stA(ch + 1);   // writes other buffer (freed by top sync)
    }
    gemm_epilogue<LOUT>(c, smem, acc, rowA0, colB0, bias, scale, C, tid);
}

__global__ void __launch_bounds__(256, 2) k_gemm2(const float* __restrict__ th1) {
    gemm_fused<0, 1>(g_hA, g_w1h, th1, g_scale[1], g_hB);
}
__global__ void __launch_bounds__(256, 2) k_gemm3(const float* __restrict__ th1) {
    gemm_fused<1, 2>(g_hB, g_w3h, th1, g_scale[2], g_hA);
}

// ---------------------- last layer + softmax + loss ------------------------
__global__ void __launch_bounds__(256) k_last(
    const float* __restrict__ thlast, const int* __restrict__ target,
    float* __restrict__ out_h, float* __restrict__ out_lp)
{
    __shared__ float msh[D_OUT][H_DIM];
    __shared__ float mush[H_DIM];
    __shared__ float rsh[H_DIM];
    __shared__ float th[D_OUT];
    __shared__ float wloss[8];
    __shared__ int   wcorr[8];

    const int tid = threadIdx.x;
    const float invM = 1.0f / (float)M_ROWS;
    for (int i = tid; i < H_DIM * D_OUT; i += 256) {
        int cc = i / H_DIM, k = i - cc * H_DIM;
        msh[cc][k] = g_mlast[k * D_OUT + cc];
    }
    for (int i = tid; i < H_DIM; i += 256) {
        float mu = g_sum[2][i] * invM;
        float var = g_sumsq[2][i] * invM - mu * mu;
        mush[i] = mu;
        rsh[i] = rsqrtf(var + BN_EPS);
    }
    if (tid < D_OUT) th[tid] = thlast[tid];
    __syncthreads();

    const int warp = tid >> 5;
    const int lane = tid & 31;
    const int row = blockIdx.x * 8 + warp;
    const float* hrow = g_hA + (size_t)row * H_DIM;

    float acc[D_OUT] = {};
    #pragma unroll 4
    for (int t = 0; t < H_DIM / 32; t++) {
        int k = t * 32 + lane;
        float xv = tanhf((hrow[k] - mush[k]) * rsh[k]);
        #pragma unroll
        for (int cc = 0; cc < D_OUT; cc++) acc[cc] = fmaf(xv, msh[cc][k], acc[cc]);
    }
    #pragma unroll
    for (int cc = 0; cc < D_OUT; cc++)
        #pragma unroll
        for (int o = 16; o; o >>= 1) acc[cc] += __shfl_xor_sync(0xFFFFFFFFu, acc[cc], o);

    if (lane == 0) {
        float lg[D_OUT];
        float mx = -1e30f;
        #pragma unroll
        for (int cc = 0; cc < D_OUT; cc++) { lg[cc] = acc[cc] + th[cc]; mx = fmaxf(mx, lg[cc]); }
        float se = 0.f;
        #pragma unroll
        for (int cc = 0; cc < D_OUT; cc++) se += expf(lg[cc] - mx);
        float lse = mx + logf(se);
        int am = 0; float bm = lg[0];
        #pragma unroll
        for (int cc = 1; cc < D_OUT; cc++) if (lg[cc] > bm) { bm = lg[cc]; am = cc; }
        #pragma unroll
        for (int cc = 0; cc < D_OUT; cc++) {
            out_h[(size_t)row * D_OUT + cc]  = lg[cc];
            out_lp[(size_t)row * D_OUT + cc] = lg[cc] - lse;
        }
        int tgt = target[row];
        wloss[warp] = -(lg[tgt] - lse);
        wcorr[warp] = (am == tgt) ? 1 : 0;
    }
    __syncthreads();
    if (tid == 0) {
        float ls = 0.f; int cc = 0;
        #pragma unroll
        for (int w = 0; w < 8; w++) { ls += wloss[w]; cc += wcorr[w]; }
        atomicAdd(&g_loss[0], ls);
        atomicAdd(&g_correct[0], cc);
    }
}
__global__ void k_finalize_out(float* __restrict__ out_tail) {
    const float inv = 1.0f / (float)M_ROWS;
    out_tail[0] = g_loss[0] * inv;
    out_tail[1] = (float)g_correct[0] * inv;
}

// ---------------------------------------------------------------------------
extern "C" void kernel_launch(void* const* d_in, const int* in_sizes, int n_in,
                              void* d_out, int out_size)
{
    (void)in_sizes; (void)n_in; (void)out_size;
    const float* x      = (const float*)d_in[0];
    const int*   target = (const int*)d_in[1];
    const float* w0     = (const float*)d_in[2];
    const float* w1     = (const float*)d_in[3];
    const float* w3     = (const float*)d_in[5];
    const float* wlast  = (const float*)d_in[6];
    const float* th0    = (const float*)d_in[7];
    const float* th1    = (const float*)d_in[8];
    const float* thlast = (const float*)d_in[10];
    float* out = (float*)d_out;

    cudaFuncSetAttribute(k_gemm1, cudaFuncAttributeMaxDynamicSharedMemorySize, SMEM_G1);
    cudaFuncSetAttribute(k_gemm2, cudaFuncAttributeMaxDynamicSharedMemorySize, SMEM_G2);
    cudaFuncSetAttribute(k_gemm3, cudaFuncAttributeMaxDynamicSharedMemorySize, SMEM_G2);

    dim3 g2(H_DIM / 128, M_ROWS / 128);

    // launch order keeps gemm1 at index 3 (the launch ncu captures)
    k_prep_w0<<<H_DIM, 256>>>(w0);                       // 0
    k_split_x<<<2048, 256>>>(x);                         // 1
    k_prep_misc<<<20, 256>>>(w0, wlast);                 // 2

    k_gemm1<<<g2, 256, SMEM_G1>>>(th0);                  // 3  <- profiled

    k_prep_w13<<<H_DIM, 256>>>(w1, w3);                  // 4
    k_diag_rows<<<128, 256>>>(w1, w3);                   // 5

    k_gemm2<<<g2, 256, SMEM_G2>>>(th1);                  // 6 (BN0+tanh fused in loader)
    k_gemm3<<<g2, 256, SMEM_G2>>>(th1);                  // 7 (BN1 fused; th1 reused, faithful)

    float* out_h  = out;
    float* out_lp = out + (size_t)M_ROWS * D_OUT;
    float* out_tl = out + (size_t)2 * M_ROWS * D_OUT;
    k_last<<<M_ROWS / 8, 256>>>(thlast, target, out_h, out_lp); // 8 (stats2 inline)
    k_finalize_out<<<1, 1>>>(out_tl);                           // 9
}

// round 16
// speedup vs baseline: 1.1896x; 1.1896x over previous
#include <cuda_runtime.h>
#include <cuda_fp16.h>
#include <math.h>
#include <stdint.h>

// ---------------------------------------------------------------------------
// EBP_binaryNet forward with mma.sync (HMMA) GEMMs (plain sm_100 PTX).
// R16 = R14 (proven 1196us) with the A-lo compensation term dropped in
// gemm2/3 (HASAL=0): activations are fp16-rounded like the weights already
// are, halving gemm2/3 MMA count. gemm1 keeps the x hi+lo split.
// ---------------------------------------------------------------------------

#define M_ROWS 65536
#define IN_DIM 784
#define K1PAD  832            // storage stride: 13 * 64
#define H_DIM  512
#define D_OUT  10
#define SQ2PI  0.79788456f
#define BN_EPS 1e-5f

#define STAGE 49152           // Ah0|Ah1 16K | Al0|Al1 16K | Bh0|Bh1 16K
#define SMEM_TOTAL (STAGE * 2)

// ------------------------- device scratch ----------------------------------
__device__ __align__(128) __half g_xh[(size_t)M_ROWS * K1PAD];
__device__ __align__(128) __half g_xl[(size_t)M_ROWS * K1PAD];
__device__ __align__(128) __half g_ah[(size_t)M_ROWS * H_DIM];
__device__ __align__(128) float  g_h[(size_t)M_ROWS * H_DIM];
__device__ __align__(128) __half g_w0h[H_DIM * K1PAD];   // [n][k]
__device__ __align__(128) __half g_w1h[H_DIM * H_DIM];
__device__ __align__(128) __half g_w3h[H_DIM * H_DIM];
__device__ float g_mlast[H_DIM * D_OUT];
__device__ float g_scale[3][H_DIM];
__device__ float g_sum[3][H_DIM];
__device__ float g_sumsq[3][H_DIM];
__device__ float g_loss[1];
__device__ int   g_correct[1];

// ------------------------- PTX helpers -------------------------------------
__device__ __forceinline__ uint32_t s2u(const void* p) {
    uint32_t a;
    asm("{ .reg .u64 t; cvta.to.shared.u64 t, %1; cvt.u32.u64 %0, t; }" : "=r"(a) : "l"(p));
    return a;
}
__device__ __forceinline__ void cp16(uint32_t s, const void* g) {
    asm volatile("cp.async.cg.shared.global [%0], [%1], 16;" :: "r"(s), "l"(g));
}
#define CP_COMMIT() asm volatile("cp.async.commit_group;" ::: "memory")
#define CP_WAIT(n)  asm volatile("cp.async.wait_group %0;" :: "n"(n) : "memory")

__device__ __forceinline__ void ldsm4(uint32_t a, uint32_t* r) {
    asm volatile("ldmatrix.sync.aligned.m8n8.x4.shared.b16 {%0,%1,%2,%3}, [%4];"
                 : "=r"(r[0]), "=r"(r[1]), "=r"(r[2]), "=r"(r[3]) : "r"(a));
}
__device__ __forceinline__ void mma16816(float* d, const uint32_t* a, const uint32_t* b) {
    asm volatile(
        "mma.sync.aligned.m16n8k16.row.col.f32.f16.f16.f32 "
        "{%0,%1,%2,%3},{%4,%5,%6,%7},{%8,%9},{%0,%1,%2,%3};"
        : "+f"(d[0]), "+f"(d[1]), "+f"(d[2]), "+f"(d[3])
        : "r"(a[0]), "r"(a[1]), "r"(a[2]), "r"(a[3]), "r"(b[0]), "r"(b[1]));
}

// swizzled byte offset of (row, 16B-unit) inside a Nx32-half sub-tile (64B rows)
__device__ __forceinline__ uint32_t swoff(int r, int u) {
    return (uint32_t)(r * 64 + ((u ^ ((r >> 1) & 3)) * 16));
}
__device__ __forceinline__ void split2(float v, __half& hi, __half& lo) {
    hi = __float2half(v);
    lo = __float2half(v - __half2float(hi));
}
__device__ __forceinline__ uint32_t pkh(__half a, __half b) {
    __half2 t = __halves2half2(a, b);
    return *reinterpret_cast<uint32_t*>(&t);
}

// ------------------------- prep kernels ------------------------------------
__global__ void k_prep_w0(const float* __restrict__ w0) {
    int n = blockIdx.x;
    // only cols [0, 800) are ever loaded by the GEMM (12 full chunks + tail sub0)
    for (int k = threadIdx.x; k < 800; k += 256) {
        float m = (k < IN_DIM) ? tanhf(0.5f * w0[k * H_DIM + n]) : 0.0f;
        g_w0h[n * K1PAD + k] = __float2half(m);
    }
}
// merged: zero stats/loss + diag_col0 + mlast prep
__global__ void k_prep_misc(const float* __restrict__ w0, const float* __restrict__ wlast) {
    int i = blockIdx.x * blockDim.x + threadIdx.x;
    if (i < 3 * H_DIM) { (&g_sum[0][0])[i] = 0.0f; (&g_sumsq[0][0])[i] = 0.0f; }
    if (i == 0) { g_loss[0] = 0.0f; g_correct[0] = 0; }
    if (i < H_DIM * D_OUT) g_mlast[i] = tanhf(0.5f * wlast[i]);
    if (i < H_DIM) {
        float s = 0.0f;
        for (int k = 0; k < IN_DIM; k++) {
            float v = tanhf(0.5f * w0[k * H_DIM + i]);
            s += 1.0f - v * v;
        }
        g_scale[0][i] = SQ2PI * rsqrtf(s);
    }
}
__global__ void k_prep_w13(const float* __restrict__ w1, const float* __restrict__ w3) {
    int n = blockIdx.x;
    for (int k = threadIdx.x; k < H_DIM; k += 256) {
        g_w1h[n * H_DIM + k] = __float2half(tanhf(0.5f * w1[k * H_DIM + n]));
        g_w3h[n * H_DIM + k] = __float2half(tanhf(0.5f * w3[k * H_DIM + n]));
    }
}
// both diag_row layers in one launch: blocks 0..63 -> w1, 64..127 -> w3
__global__ void k_diag_rows(const float* __restrict__ w1, const float* __restrict__ w3) {
    int gb = blockIdx.x;
    const float* w = (gb < 64) ? w1 : w3;
    const int L = (gb < 64) ? 1 : 2;
    int row = ((gb & 63) * 256 + threadIdx.x) >> 5;
    int lane = threadIdx.x & 31;
    if (row >= H_DIM) return;
    float s = 0.0f;
    #pragma unroll
    for (int t = 0; t < H_DIM / 32; t++) {
        float v = tanhf(0.5f * w[row * H_DIM + t * 32 + lane]);
        s += 1.0f - v * v;
    }
    #pragma unroll
    for (int o = 16; o; o >>= 1) s += __shfl_xor_sync(0xFFFFFFFFu, s, o);
    if (lane == 0) g_scale[L][row] = SQ2PI * rsqrtf(s);
}
// x split: grid-strided float4 over real data; zero only cols [784, 800)
__global__ void __launch_bounds__(256) k_split_x(const float* __restrict__ x) {
    const int tid = blockIdx.x * 256 + threadIdx.x;
    const int nreal = M_ROWS * (IN_DIM / 4);        // 196 float4 per row
    const float4* xv = reinterpret_cast<const float4*>(x);
    uint2* oh = reinterpret_cast<uint2*>(g_xh);
    uint2* ol = reinterpret_cast<uint2*>(g_xl);
    for (int idx = tid; idx < nreal; idx += gridDim.x * 256) {
        const int row = idx / (IN_DIM / 4);
        const int c4  = idx - row * (IN_DIM / 4);
        float4 v = xv[idx];
        __half h0, l0, h1, l1, h2, l2, h3, l3;
        split2(v.x, h0, l0); split2(v.y, h1, l1);
        split2(v.z, h2, l2); split2(v.w, h3, l3);
        const int o = row * (K1PAD / 4) + c4;
        oh[o] = make_uint2(pkh(h0, h1), pkh(h2, h3));
        ol[o] = make_uint2(pkh(l0, l1), pkh(l2, l3));
    }
    // pad columns [784, 800): 4 uint2 per row (tail sub covers cols 768..799)
    const int npad = M_ROWS * 4;
    for (int idx = tid; idx < npad; idx += gridDim.x * 256) {
        const int row = idx >> 2;
        const int c4  = idx & 3;
        const int o = row * (K1PAD / 4) + (IN_DIM / 4) + c4;
        oh[o] = make_uint2(0u, 0u);
        ol[o] = make_uint2(0u, 0u);
    }
}
// BN finalize (from raw sums) + tanh + fp16 round (no lo term), grid-strided
template <int L>
__global__ void __launch_bounds__(256) k_split_act() {
    __shared__ float s_mu[H_DIM], s_rs[H_DIM];
    const int tid = threadIdx.x;
    const float inv = 1.0f / (float)M_ROWS;
    for (int i = tid; i < H_DIM; i += 256) {
        float mu = g_sum[L][i] * inv;
        float var = g_sumsq[L][i] * inv - mu * mu;
        s_mu[i] = mu;
        s_rs[i] = rsqrtf(var + BN_EPS);
    }
    __syncthreads();
    const int total = M_ROWS * (H_DIM / 4);
    const float4* hv = reinterpret_cast<const float4*>(g_h);
    uint2* oh = reinterpret_cast<uint2*>(g_ah);
    for (int idx = blockIdx.x * 256 + tid; idx < total; idx += gridDim.x * 256) {
        const int c0 = (idx & 127) * 4;
        float4 v = hv[idx];
        float a0 = tanhf((v.x - s_mu[c0 + 0]) * s_rs[c0 + 0]);
        float a1 = tanhf((v.y - s_mu[c0 + 1]) * s_rs[c0 + 1]);
        float a2 = tanhf((v.z - s_mu[c0 + 2]) * s_rs[c0 + 2]);
        float a3 = tanhf((v.w - s_mu[c0 + 3]) * s_rs[c0 + 3]);
        oh[idx] = make_uint2(pkh(__float2half(a0), __float2half(a1)),
                             pkh(__float2half(a2), __float2half(a3)));
    }
}

// ------------------------- mma.sync GEMM -----------------------------------
// C[128 x 128 per CTA] = (A @ Bh^T + bias[c]) * scale[c]
// HASAL=1: A = Ah + Al (hi/lo split).  HASAL=0: A = Ah only.
// Fused epilogue column stats -> g_sum/g_sumsq[LOUT].
// 8 warps (4m x 2n), warp tile 32x64, K-chunk 64 (two 32-col sub-tiles),
// 2-stage, 1 syncthreads per chunk. TAIL=1: last chunk = 16 real cols.
template <int LOUT, int K, int NK, int TAIL, int HASAL>
__device__ __forceinline__ void gemm_mma(
    const __half* __restrict__ Ah, const __half* __restrict__ Al,
    const __half* __restrict__ Bh,
    const float* __restrict__ bias, const float* __restrict__ scale,
    float* __restrict__ C)
{
    extern __shared__ __align__(128) char smem[];
    const uint32_t sbase = s2u(smem);
    const int tid = threadIdx.x, lane = tid & 31, wid = tid >> 5;
    const int rowA0 = blockIdx.y * 128, colB0 = blockIdx.x * 128;
    const int wm = wid >> 1, wn = wid & 1;

    const int r  = tid >> 1;
    const int hs = tid & 1;
    const __half* pAh = Ah + (size_t)(rowA0 + r) * K + hs * 16;
    const __half* pAl = HASAL ? (Al + (size_t)(rowA0 + r) * K + hs * 16) : nullptr;
    const __half* pBh = Bh + (size_t)(colB0 + r) * K + hs * 16;
    const uint32_t so0 = swoff(r, hs * 2);
    const uint32_t so1 = swoff(r, hs * 2 + 1);

    const int ar = wm * 32 + (lane & 7) + ((lane >> 3) & 1) * 8;
    const int au = lane >> 4;
    const int br = wn * 64 + (lane & 7) + (lane >> 4) * 8;
    const int bu = (lane >> 3) & 1;
    uint32_t a_off[2][2], b_off[4][2];
    #pragma unroll
    for (int mt = 0; mt < 2; mt++)
        #pragma unroll
        for (int ks = 0; ks < 2; ks++) a_off[mt][ks] = swoff(ar + mt * 16, au + 2 * ks);
    #pragma unroll
    for (int nb = 0; nb < 4; nb++)
        #pragma unroll
        for (int ks = 0; ks < 2; ks++) b_off[nb][ks] = swoff(br + nb * 16, bu + 2 * ks);

    float acc[2][8][4] = {};

    auto issue = [&](int ch) {
        const uint32_t sb = sbase + (ch & 1) * STAGE;
        const int nsub = (TAIL && ch == NK - 1) ? 1 : 2;
        for (int sub = 0; sub < nsub; sub++) {
            const size_t kk = (size_t)ch * 64 + sub * 32;
            const uint32_t st = sb + sub * 8192;
            cp16(st +         so0, pAh + kk);  cp16(st +         so1, pAh + kk + 8);
            if (HASAL) {
                cp16(st + 16384 + so0, pAl + kk);  cp16(st + 16384 + so1, pAl + kk + 8);
            }
            cp16(st + 32768 + so0, pBh + kk);  cp16(st + 32768 + so1, pBh + kk + 8);
        }
    };

    issue(0); CP_COMMIT();
    for (int ch = 0; ch < NK; ch++) {
        CP_WAIT(0);
        __syncthreads();   // chunk ch visible everywhere; compute(ch-1) done
        if (ch + 1 < NK) { issue(ch + 1); CP_COMMIT(); }

        const uint32_t sbc = sbase + (ch & 1) * STAGE;
        if (TAIL && ch == NK - 1) {
            // tail: 16 real cols -> sub0, ks0 only
            uint32_t ah[2][4], al[2][4], bh[4];
            ldsm4(sbc + a_off[0][0], ah[0]);
            ldsm4(sbc + a_off[1][0], ah[1]);
            if (HASAL) {
                ldsm4(sbc + 16384 + a_off[0][0], al[0]);
                ldsm4(sbc + 16384 + a_off[1][0], al[1]);
            }
            #pragma unroll
            for (int nb = 0; nb < 4; nb++) {
                ldsm4(sbc + 32768 + b_off[nb][0], bh);
                mma16816(acc[0][2 * nb],     ah[0], bh);
                mma16816(acc[1][2 * nb],     ah[1], bh);
                mma16816(acc[0][2 * nb + 1], ah[0], bh + 2);
                mma16816(acc[1][2 * nb + 1], ah[1], bh + 2);
                if (HASAL) {
                    mma16816(acc[0][2 * nb],     al[0], bh);
                    mma16816(acc[1][2 * nb],     al[1], bh);
                    mma16816(acc[0][2 * nb + 1], al[0], bh + 2);
                    mma16816(acc[1][2 * nb + 1], al[1], bh + 2);
                }
            }
        } else {
            #pragma unroll
            for (int sub = 0; sub < 2; sub++) {
                const uint32_t sb = sbc + sub * 8192;
                #pragma unroll
                for (int ks = 0; ks < 2; ks++) {
                    uint32_t ah[2][4], al[2][4];
                    ldsm4(sb + a_off[0][ks], ah[0]);
                    ldsm4(sb + a_off[1][ks], ah[1]);
                    if (HASAL) {
                        ldsm4(sb + 16384 + a_off[0][ks], al[0]);
                        ldsm4(sb + 16384 + a_off[1][ks], al[1]);
                    }
                    #pragma unroll
                    for (int nb = 0; nb < 4; nb++) {
                        uint32_t bh[4];
                        ldsm4(sb + 32768 + b_off[nb][ks], bh);
                        mma16816(acc[0][2 * nb],     ah[0], bh);
                        mma16816(acc[1][2 * nb],     ah[1], bh);
                        mma16816(acc[0][2 * nb + 1], ah[0], bh + 2);
                        mma16816(acc[1][2 * nb + 1], ah[1], bh + 2);
                        if (HASAL) {
                            mma16816(acc[0][2 * nb],     al[0], bh);
                            mma16816(acc[1][2 * nb],     al[1], bh);
                            mma16816(acc[0][2 * nb + 1], al[0], bh + 2);
                            mma16816(acc[1][2 * nb + 1], al[1], bh + 2);
                        }
                    }
                }
            }
        }
    }

    // --- epilogue: (acc + bias)*scale -> C, plus fused column sum/sumsq ---
    __syncthreads();
    float* s_sum = reinterpret_cast<float*>(smem);
    float* s_sq  = s_sum + 128;
    if (tid < 256) reinterpret_cast<float*>(smem)[tid] = 0.0f;
    __syncthreads();

    #pragma unroll
    for (int nt = 0; nt < 8; nt++) {
        const int cl = wn * 64 + nt * 8 + 2 * (lane & 3);
        const int col = colB0 + cl;
        const float b0 = __ldg(bias + col),     sc0 = __ldg(scale + col);
        const float b1 = __ldg(bias + col + 1), sc1 = __ldg(scale + col + 1);
        float cs0 = 0.f, cq0 = 0.f, cs1 = 0.f, cq1 = 0.f;
        #pragma unroll
        for (int mt = 0; mt < 2; mt++) {
            const int row0 = rowA0 + wm * 32 + mt * 16 + (lane >> 2);
            float2 o0, o1;
            o0.x = (acc[mt][nt][0] + b0) * sc0;
            o0.y = (acc[mt][nt][1] + b1) * sc1;
            o1.x = (acc[mt][nt][2] + b0) * sc0;
            o1.y = (acc[mt][nt][3] + b1) * sc1;
            *reinterpret_cast<float2*>(C + (size_t)row0 * H_DIM + col)       = o0;
            *reinterpret_cast<float2*>(C + (size_t)(row0 + 8) * H_DIM + col) = o1;
            cs0 += o0.x + o1.x;  cq0 += o0.x * o0.x + o1.x * o1.x;
            cs1 += o0.y + o1.y;  cq1 += o0.y * o0.y + o1.y * o1.y;
        }
        #pragma unroll
        for (int off = 4; off <= 16; off <<= 1) {
            cs0 += __shfl_xor_sync(0xFFFFFFFFu, cs0, off);
            cq0 += __shfl_xor_sync(0xFFFFFFFFu, cq0, off);
            cs1 += __shfl_xor_sync(0xFFFFFFFFu, cs1, off);
            cq1 += __shfl_xor_sync(0xFFFFFFFFu, cq1, off);
        }
        if ((lane >> 2) == 0) {
            atomicAdd(&s_sum[cl], cs0);     atomicAdd(&s_sq[cl], cq0);
            atomicAdd(&s_sum[cl + 1], cs1); atomicAdd(&s_sq[cl + 1], cq1);
        }
    }
    __syncthreads();
    if (tid < 128) {
        atomicAdd(&g_sum[LOUT][colB0 + tid], s_sum[tid]);
        atomicAdd(&g_sumsq[LOUT][colB0 + tid], s_sq[tid]);
    }
}

__global__ void __launch_bounds__(256, 2) k_gemm1(const float* __restrict__ th0) {
    gemm_mma<0, K1PAD, 13, 1, 1>(g_xh, g_xl, g_w0h, th0, g_scale[0], g_h);
}
__global__ void __launch_bounds__(256, 2) k_gemm2(const float* __restrict__ th1) {
    gemm_mma<1, H_DIM, 8, 0, 0>(g_ah, nullptr, g_w1h, th1, g_scale[1], g_h);
}
__global__ void __launch_bounds__(256, 2) k_gemm3(const float* __restrict__ th1) {
    gemm_mma<2, H_DIM, 8, 0, 0>(g_ah, nullptr, g_w3h, th1, g_scale[2], g_h);
}

// ---------------------- last layer + softmax + loss ------------------------
__global__ void __launch_bounds__(256) k_last(
    const float* __restrict__ thlast, const int* __restrict__ target,
    float* __restrict__ out_h, float* __restrict__ out_lp)
{
    __shared__ float msh[D_OUT][H_DIM];
    __shared__ float mush[H_DIM];
    __shared__ float rsh[H_DIM];
    __shared__ float th[D_OUT];
    __shared__ float wloss[8];
    __shared__ int   wcorr[8];

    const int tid = threadIdx.x;
    const float invM = 1.0f / (float)M_ROWS;
    for (int i = tid; i < H_DIM * D_OUT; i += 256) {
        int c = i / H_DIM, k = i - c * H_DIM;
        msh[c][k] = g_mlast[k * D_OUT + c];
    }
    for (int i = tid; i < H_DIM; i += 256) {
        float mu = g_sum[2][i] * invM;
        float var = g_sumsq[2][i] * invM - mu * mu;
        mush[i] = mu;
        rsh[i] = rsqrtf(var + BN_EPS);
    }
    if (tid < D_OUT) th[tid] = thlast[tid];
    __syncthreads();

    const int warp = tid >> 5;
    const int lane = tid & 31;
    const int row = blockIdx.x * 8 + warp;
    const float* hrow = g_h + (size_t)row * H_DIM;

    float acc[D_OUT] = {};
    #pragma unroll 4
    for (int t = 0; t < H_DIM / 32; t++) {
        int k = t * 32 + lane;
        float xv = tanhf((hrow[k] - mush[k]) * rsh[k]);
        #pragma unroll
        for (int c = 0; c < D_OUT; c++) acc[c] = fmaf(xv, msh[c][k], acc[c]);
    }
    #pragma unroll
    for (int c = 0; c < D_OUT; c++)
        #pragma unroll
        for (int o = 16; o; o >>= 1) acc[c] += __shfl_xor_sync(0xFFFFFFFFu, acc[c], o);

    if (lane == 0) {
        float lg[D_OUT];
        float mx = -1e30f;
        #pragma unroll
        for (int c = 0; c < D_OUT; c++) { lg[c] = acc[c] + th[c]; mx = fmaxf(mx, lg[c]); }
        float se = 0.f;
        #pragma unroll
        for (int c = 0; c < D_OUT; c++) se += expf(lg[c] - mx);
        float lse = mx + logf(se);
        int am = 0; float bm = lg[0];
        #pragma unroll
        for (int c = 1; c < D_OUT; c++) if (lg[c] > bm) { bm = lg[c]; am = c; }
        #pragma unroll
        for (int c = 0; c < D_OUT; c++) {
            out_h[(size_t)row * D_OUT + c]  = lg[c];
            out_lp[(size_t)row * D_OUT + c] = lg[c] - lse;
        }
        int tgt = target[row];
        wloss[warp] = -(lg[tgt] - lse);
        wcorr[warp] = (am == tgt) ? 1 : 0;
    }
    __syncthreads();
    if (tid == 0) {
        float ls = 0.f; int cc = 0;
        #pragma unroll
        for (int w = 0; w < 8; w++) { ls += wloss[w]; cc += wcorr[w]; }
        atomicAdd(&g_loss[0], ls);
        atomicAdd(&g_correct[0], cc);
    }
}
__global__ void k_finalize_out(float* __restrict__ out_tail) {
    const float inv = 1.0f / (float)M_ROWS;
    out_tail[0] = g_loss[0] * inv;
    out_tail[1] = (float)g_correct[0] * inv;
}

// ---------------------------------------------------------------------------
extern "C" void kernel_launch(void* const* d_in, const int* in_sizes, int n_in,
                              void* d_out, int out_size)
{
    (void)in_sizes; (void)n_in; (void)out_size;
    const float* x      = (const float*)d_in[0];
    const int*   target = (const int*)d_in[1];
    const float* w0     = (const float*)d_in[2];
    const float* w1     = (const float*)d_in[3];
    const float* w3     = (const float*)d_in[5];
    const float* wlast  = (const float*)d_in[6];
    const float* th0    = (const float*)d_in[7];
    const float* th1    = (const float*)d_in[8];
    const float* thlast = (const float*)d_in[10];
    float* out = (float*)d_out;

    cudaFuncSetAttribute(k_gemm1, cudaFuncAttributeMaxDynamicSharedMemorySize, SMEM_TOTAL);
    cudaFuncSetAttribute(k_gemm2, cudaFuncAttributeMaxDynamicSharedMemorySize, SMEM_TOTAL);
    cudaFuncSetAttribute(k_gemm3, cudaFuncAttributeMaxDynamicSharedMemorySize, SMEM_TOTAL);

    dim3 g2(H_DIM / 128, M_ROWS / 128);

    // launch order keeps gemm1 at index 3 (the launch ncu captures)
    k_prep_w0<<<H_DIM, 256>>>(w0);                       // 0
    k_split_x<<<2048, 256>>>(x);                         // 1
    k_prep_misc<<<20, 256>>>(w0, wlast);                 // 2

    k_gemm1<<<g2, 256, SMEM_TOTAL>>>(th0);               // 3  <- profiled

    k_prep_w13<<<H_DIM, 256>>>(w1, w3);                  // 4
    k_diag_rows<<<128, 256>>>(w1, w3);                   // 5
    k_split_act<0><<<2048, 256>>>();                     // 6 (stats0 inline)

    k_gemm2<<<g2, 256, SMEM_TOTAL>>>(th1);               // 7
    k_split_act<1><<<2048, 256>>>();                     // 8 (stats1 inline)

    k_gemm3<<<g2, 256, SMEM_TOTAL>>>(th1);               // 9 (th1 reused, faithful)

    float* out_h  = out;
    float* out_lp = out + (size_t)M_ROWS * D_OUT;
    float* out_tl = out + (size_t)2 * M_ROWS * D_OUT;
    k_last<<<M_ROWS / 8, 256>>>(thlast, target, out_h, out_lp); // 10 (stats2 inline)
    k_finalize_out<<<1, 1>>>(out_tl);                           // 11
}

// round 17
// speedup vs baseline: 1.3821x; 1.1618x over previous
#include <cuda_runtime.h>
#include <cuda_fp16.h>
#include <math.h>
#include <stdint.h>

// ---------------------------------------------------------------------------
// EBP_binaryNet forward with mma.sync (HMMA) GEMMs (plain sm_100 PTX).
// R17 = R16 with gemm1's A-lo term dropped as well (pure fp16 operands
// everywhere, fp32 accumulate). Calibrated quadrature error model predicts
// rel_err ~6.5e-4 vs 1e-3 threshold.
// ---------------------------------------------------------------------------

#define M_ROWS 65536
#define IN_DIM 784
#define K1PAD  832            // storage stride: 13 * 64
#define H_DIM  512
#define D_OUT  10
#define SQ2PI  0.79788456f
#define BN_EPS 1e-5f

#define STAGE 49152           // Ah0|Ah1 16K | (hole) | Bh0|Bh1 16K
#define SMEM_TOTAL (STAGE * 2)

// ------------------------- device scratch ----------------------------------
__device__ __align__(128) __half g_xh[(size_t)M_ROWS * K1PAD];
__device__ __align__(128) __half g_ah[(size_t)M_ROWS * H_DIM];
__device__ __align__(128) float  g_h[(size_t)M_ROWS * H_DIM];
__device__ __align__(128) __half g_w0h[H_DIM * K1PAD];   // [n][k]
__device__ __align__(128) __half g_w1h[H_DIM * H_DIM];
__device__ __align__(128) __half g_w3h[H_DIM * H_DIM];
__device__ float g_mlast[H_DIM * D_OUT];
__device__ float g_scale[3][H_DIM];
__device__ float g_sum[3][H_DIM];
__device__ float g_sumsq[3][H_DIM];
__device__ float g_loss[1];
__device__ int   g_correct[1];

// ------------------------- PTX helpers -------------------------------------
__device__ __forceinline__ uint32_t s2u(const void* p) {
    uint32_t a;
    asm("{ .reg .u64 t; cvta.to.shared.u64 t, %1; cvt.u32.u64 %0, t; }" : "=r"(a) : "l"(p));
    return a;
}
__device__ __forceinline__ void cp16(uint32_t s, const void* g) {
    asm volatile("cp.async.cg.shared.global [%0], [%1], 16;" :: "r"(s), "l"(g));
}
#define CP_COMMIT() asm volatile("cp.async.commit_group;" ::: "memory")
#define CP_WAIT(n)  asm volatile("cp.async.wait_group %0;" :: "n"(n) : "memory")

__device__ __forceinline__ void ldsm4(uint32_t a, uint32_t* r) {
    asm volatile("ldmatrix.sync.aligned.m8n8.x4.shared.b16 {%0,%1,%2,%3}, [%4];"
                 : "=r"(r[0]), "=r"(r[1]), "=r"(r[2]), "=r"(r[3]) : "r"(a));
}
__device__ __forceinline__ void mma16816(float* d, const uint32_t* a, const uint32_t* b) {
    asm volatile(
        "mma.sync.aligned.m16n8k16.row.col.f32.f16.f16.f32 "
        "{%0,%1,%2,%3},{%4,%5,%6,%7},{%8,%9},{%0,%1,%2,%3};"
        : "+f"(d[0]), "+f"(d[1]), "+f"(d[2]), "+f"(d[3])
        : "r"(a[0]), "r"(a[1]), "r"(a[2]), "r"(a[3]), "r"(b[0]), "r"(b[1]));
}

// swizzled byte offset of (row, 16B-unit) inside a Nx32-half sub-tile (64B rows)
__device__ __forceinline__ uint32_t swoff(int r, int u) {
    return (uint32_t)(r * 64 + ((u ^ ((r >> 1) & 3)) * 16));
}
__device__ __forceinline__ uint32_t pkh(__half a, __half b) {
    __half2 t = __halves2half2(a, b);
    return *reinterpret_cast<uint32_t*>(&t);
}

// ------------------------- prep kernels ------------------------------------
__global__ void k_prep_w0(const float* __restrict__ w0) {
    int n = blockIdx.x;
    // only cols [0, 800) are ever loaded by the GEMM (12 full chunks + tail sub0)
    for (int k = threadIdx.x; k < 800; k += 256) {
        float m = (k < IN_DIM) ? tanhf(0.5f * w0[k * H_DIM + n]) : 0.0f;
        g_w0h[n * K1PAD + k] = __float2half(m);
    }
}
// merged: zero stats/loss + diag_col0 + mlast prep
__global__ void k_prep_misc(const float* __restrict__ w0, const float* __restrict__ wlast) {
    int i = blockIdx.x * blockDim.x + threadIdx.x;
    if (i < 3 * H_DIM) { (&g_sum[0][0])[i] = 0.0f; (&g_sumsq[0][0])[i] = 0.0f; }
    if (i == 0) { g_loss[0] = 0.0f; g_correct[0] = 0; }
    if (i < H_DIM * D_OUT) g_mlast[i] = tanhf(0.5f * wlast[i]);
    if (i < H_DIM) {
        float s = 0.0f;
        for (int k = 0; k < IN_DIM; k++) {
            float v = tanhf(0.5f * w0[k * H_DIM + i]);
            s += 1.0f - v * v;
        }
        g_scale[0][i] = SQ2PI * rsqrtf(s);
    }
}
__global__ void k_prep_w13(const float* __restrict__ w1, const float* __restrict__ w3) {
    int n = blockIdx.x;
    for (int k = threadIdx.x; k < H_DIM; k += 256) {
        g_w1h[n * H_DIM + k] = __float2half(tanhf(0.5f * w1[k * H_DIM + n]));
        g_w3h[n * H_DIM + k] = __float2half(tanhf(0.5f * w3[k * H_DIM + n]));
    }
}
// both diag_row layers in one launch: blocks 0..63 -> w1, 64..127 -> w3
__global__ void k_diag_rows(const float* __restrict__ w1, const float* __restrict__ w3) {
    int gb = blockIdx.x;
    const float* w = (gb < 64) ? w1 : w3;
    const int L = (gb < 64) ? 1 : 2;
    int row = ((gb & 63) * 256 + threadIdx.x) >> 5;
    int lane = threadIdx.x & 31;
    if (row >= H_DIM) return;
    float s = 0.0f;
    #pragma unroll
    for (int t = 0; t < H_DIM / 32; t++) {
        float v = tanhf(0.5f * w[row * H_DIM + t * 32 + lane]);
        s += 1.0f - v * v;
    }
    #pragma unroll
    for (int o = 16; o; o >>= 1) s += __shfl_xor_sync(0xFFFFFFFFu, s, o);
    if (lane == 0) g_scale[L][row] = SQ2PI * rsqrtf(s);
}
// x -> fp16, grid-strided float4; zero only cols [784, 800)
__global__ void __launch_bounds__(256) k_split_x(const float* __restrict__ x) {
    const int tid = blockIdx.x * 256 + threadIdx.x;
    const int nreal = M_ROWS * (IN_DIM / 4);        // 196 float4 per row
    const float4* xv = reinterpret_cast<const float4*>(x);
    uint2* oh = reinterpret_cast<uint2*>(g_xh);
    for (int idx = tid; idx < nreal; idx += gridDim.x * 256) {
        const int row = idx / (IN_DIM / 4);
        const int c4  = idx - row * (IN_DIM / 4);
        float4 v = xv[idx];
        const int o = row * (K1PAD / 4) + c4;
        oh[o] = make_uint2(pkh(__float2half(v.x), __float2half(v.y)),
                           pkh(__float2half(v.z), __float2half(v.w)));
    }
    // pad columns [784, 800): 4 uint2 per row (tail sub covers cols 768..799)
    const int npad = M_ROWS * 4;
    for (int idx = tid; idx < npad; idx += gridDim.x * 256) {
        const int row = idx >> 2;
        const int c4  = idx & 3;
        const int o = row * (K1PAD / 4) + (IN_DIM / 4) + c4;
        oh[o] = make_uint2(0u, 0u);
    }
}
// BN finalize (from raw sums) + tanh + fp16 round, grid-strided float4
template <int L>
__global__ void __launch_bounds__(256) k_split_act() {
    __shared__ float s_mu[H_DIM], s_rs[H_DIM];
    const int tid = threadIdx.x;
    const float inv = 1.0f / (float)M_ROWS;
    for (int i = tid; i < H_DIM; i += 256) {
        float mu = g_sum[L][i] * inv;
        float var = g_sumsq[L][i] * inv - mu * mu;
        s_mu[i] = mu;
        s_rs[i] = rsqrtf(var + BN_EPS);
    }
    __syncthreads();
    const int total = M_ROWS * (H_DIM / 4);
    const float4* hv = reinterpret_cast<const float4*>(g_h);
    uint2* oh = reinterpret_cast<uint2*>(g_ah);
    for (int idx = blockIdx.x * 256 + tid; idx < total; idx += gridDim.x * 256) {
        const int c0 = (idx & 127) * 4;
        float4 v = hv[idx];
        float a0 = tanhf((v.x - s_mu[c0 + 0]) * s_rs[c0 + 0]);
        float a1 = tanhf((v.y - s_mu[c0 + 1]) * s_rs[c0 + 1]);
        float a2 = tanhf((v.z - s_mu[c0 + 2]) * s_rs[c0 + 2]);
        float a3 = tanhf((v.w - s_mu[c0 + 3]) * s_rs[c0 + 3]);
        oh[idx] = make_uint2(pkh(__float2half(a0), __float2half(a1)),
                             pkh(__float2half(a2), __float2half(a3)));
    }
}

// ------------------------- mma.sync GEMM -----------------------------------
// C[128 x 128 per CTA] = (Ah @ Bh^T + bias[c]) * scale[c], fp32 accumulate.
// Fused epilogue column stats -> g_sum/g_sumsq[LOUT].
// 8 warps (4m x 2n), warp tile 32x64, K-chunk 64 (two 32-col sub-tiles),
// 2-stage, 1 syncthreads per chunk. TAIL=1: last chunk = 16 real cols.
template <int LOUT, int K, int NK, int TAIL>
__device__ __forceinline__ void gemm_mma(
    const __half* __restrict__ Ah, const __half* __restrict__ Bh,
    const float* __restrict__ bias, const float* __restrict__ scale,
    float* __restrict__ C)
{
    extern __shared__ __align__(128) char smem[];
    const uint32_t sbase = s2u(smem);
    const int tid = threadIdx.x, lane = tid & 31, wid = tid >> 5;
    const int rowA0 = blockIdx.y * 128, colB0 = blockIdx.x * 128;
    const int wm = wid >> 1, wn = wid & 1;

    const int r  = tid >> 1;
    const int hs = tid & 1;
    const __half* pAh = Ah + (size_t)(rowA0 + r) * K + hs * 16;
    const __half* pBh = Bh + (size_t)(colB0 + r) * K + hs * 16;
    const uint32_t so0 = swoff(r, hs * 2);
    const uint32_t so1 = swoff(r, hs * 2 + 1);

    const int ar = wm * 32 + (lane & 7) + ((lane >> 3) & 1) * 8;
    const int au = lane >> 4;
    const int br = wn * 64 + (lane & 7) + (lane >> 4) * 8;
    const int bu = (lane >> 3) & 1;
    uint32_t a_off[2][2], b_off[4][2];
    #pragma unroll
    for (int mt = 0; mt < 2; mt++)
        #pragma unroll
        for (int ks = 0; ks < 2; ks++) a_off[mt][ks] = swoff(ar + mt * 16, au + 2 * ks);
    #pragma unroll
    for (int nb = 0; nb < 4; nb++)
        #pragma unroll
        for (int ks = 0; ks < 2; ks++) b_off[nb][ks] = swoff(br + nb * 16, bu + 2 * ks);

    float acc[2][8][4] = {};

    auto issue = [&](int ch) {
        const uint32_t sb = sbase + (ch & 1) * STAGE;
        const int nsub = (TAIL && ch == NK - 1) ? 1 : 2;
        for (int sub = 0; sub < nsub; sub++) {
            const size_t kk = (size_t)ch * 64 + sub * 32;
            const uint32_t st = sb + sub * 8192;
            cp16(st +         so0, pAh + kk);  cp16(st +         so1, pAh + kk + 8);
            cp16(st + 32768 + so0, pBh + kk);  cp16(st + 32768 + so1, pBh + kk + 8);
        }
    };

    issue(0); CP_COMMIT();
    for (int ch = 0; ch < NK; ch++) {
        CP_WAIT(0);
        __syncthreads();   // chunk ch visible everywhere; compute(ch-1) done
        if (ch + 1 < NK) { issue(ch + 1); CP_COMMIT(); }

        const uint32_t sbc = sbase + (ch & 1) * STAGE;
        if (TAIL && ch == NK - 1) {
            // tail: 16 real cols -> sub0, ks0 only
            uint32_t ah[2][4], bh[4];
            ldsm4(sbc + a_off[0][0], ah[0]);
            ldsm4(sbc + a_off[1][0], ah[1]);
            #pragma unroll
            for (int nb = 0; nb < 4; nb++) {
                ldsm4(sbc + 32768 + b_off[nb][0], bh);
                mma16816(acc[0][2 * nb],     ah[0], bh);
                mma16816(acc[1][2 * nb],     ah[1], bh);
                mma16816(acc[0][2 * nb + 1], ah[0], bh + 2);
                mma16816(acc[1][2 * nb + 1], ah[1], bh + 2);
            }
        } else {
            #pragma unroll
            for (int sub = 0; sub < 2; sub++) {
                const uint32_t sb = sbc + sub * 8192;
                #pragma unroll
                for (int ks = 0; ks < 2; ks++) {
                    uint32_t ah[2][4];
                    ldsm4(sb + a_off[0][ks], ah[0]);
                    ldsm4(sb + a_off[1][ks], ah[1]);
                    #pragma unroll
                    for (int nb = 0; nb < 4; nb++) {
                        uint32_t bh[4];
                        ldsm4(sb + 32768 + b_off[nb][ks], bh);
                        mma16816(acc[0][2 * nb],     ah[0], bh);
                        mma16816(acc[1][2 * nb],     ah[1], bh);
                        mma16816(acc[0][2 * nb + 1], ah[0], bh + 2);
                        mma16816(acc[1][2 * nb + 1], ah[1], bh + 2);
                    }
                }
            }
        }
    }

    // --- epilogue: (acc + bias)*scale -> C, plus fused column sum/sumsq ---
    __syncthreads();
    float* s_sum = reinterpret_cast<float*>(smem);
    float* s_sq  = s_sum + 128;
    if (tid < 256) reinterpret_cast<float*>(smem)[tid] = 0.0f;
    __syncthreads();

    #pragma unroll
    for (int nt = 0; nt < 8; nt++) {
        const int cl = wn * 64 + nt * 8 + 2 * (lane & 3);
        const int col = colB0 + cl;
        const float b0 = __ldg(bias + col),     sc0 = __ldg(scale + col);
        const float b1 = __ldg(bias + col + 1), sc1 = __ldg(scale + col + 1);
        float cs0 = 0.f, cq0 = 0.f, cs1 = 0.f, cq1 = 0.f;
        #pragma unroll
        for (int mt = 0; mt < 2; mt++) {
            const int row0 = rowA0 + wm * 32 + mt * 16 + (lane >> 2);
            float2 o0, o1;
            o0.x = (acc[mt][nt][0] + b0) * sc0;
            o0.y = (acc[mt][nt][1] + b1) * sc1;
            o1.x = (acc[mt][nt][2] + b0) * sc0;
            o1.y = (acc[mt][nt][3] + b1) * sc1;
            *reinterpret_cast<float2*>(C + (size_t)row0 * H_DIM + col)       = o0;
            *reinterpret_cast<float2*>(C + (size_t)(row0 + 8) * H_DIM + col) = o1;
            cs0 += o0.x + o1.x;  cq0 += o0.x * o0.x + o1.x * o1.x;
            cs1 += o0.y + o1.y;  cq1 += o0.y * o0.y + o1.y * o1.y;
        }
        #pragma unroll
        for (int off = 4; off <= 16; off <<= 1) {
            cs0 += __shfl_xor_sync(0xFFFFFFFFu, cs0, off);
            cq0 += __shfl_xor_sync(0xFFFFFFFFu, cq0, off);
            cs1 += __shfl_xor_sync(0xFFFFFFFFu, cs1, off);
            cq1 += __shfl_xor_sync(0xFFFFFFFFu, cq1, off);
        }
        if ((lane >> 2) == 0) {
            atomicAdd(&s_sum[cl], cs0);     atomicAdd(&s_sq[cl], cq0);
            atomicAdd(&s_sum[cl + 1], cs1); atomicAdd(&s_sq[cl + 1], cq1);
        }
    }
    __syncthreads();
    if (tid < 128) {
        atomicAdd(&g_sum[LOUT][colB0 + tid], s_sum[tid]);
        atomicAdd(&g_sumsq[LOUT][colB0 + tid], s_sq[tid]);
    }
}

__global__ void __launch_bounds__(256, 2) k_gemm1(const float* __restrict__ th0) {
    gemm_mma<0, K1PAD, 13, 1>(g_xh, g_w0h, th0, g_scale[0], g_h);
}
__global__ void __launch_bounds__(256, 2) k_gemm2(const float* __restrict__ th1) {
    gemm_mma<1, H_DIM, 8, 0>(g_ah, g_w1h, th1, g_scale[1], g_h);
}
__global__ void __launch_bounds__(256, 2) k_gemm3(const float* __restrict__ th1) {
    gemm_mma<2, H_DIM, 8, 0>(g_ah, g_w3h, th1, g_scale[2], g_h);
}

// ---------------------- last layer + softmax + loss ------------------------
__global__ void __launch_bounds__(256) k_last(
    const float* __restrict__ thlast, const int* __restrict__ target,
    float* __restrict__ out_h, float* __restrict__ out_lp)
{
    __shared__ float msh[D_OUT][H_DIM];
    __shared__ float mush[H_DIM];
    __shared__ float rsh[H_DIM];
    __shared__ float th[D_OUT];
    __shared__ float wloss[8];
    __shared__ int   wcorr[8];

    const int tid = threadIdx.x;
    const float invM = 1.0f / (float)M_ROWS;
    for (int i = tid; i < H_DIM * D_OUT; i += 256) {
        int c = i / H_DIM, k = i - c * H_DIM;
        msh[c][k] = g_mlast[k * D_OUT + c];
    }
    for (int i = tid; i < H_DIM; i += 256) {
        float mu = g_sum[2][i] * invM;
        float var = g_sumsq[2][i] * invM - mu * mu;
        mush[i] = mu;
        rsh[i] = rsqrtf(var + BN_EPS);
    }
    if (tid < D_OUT) th[tid] = thlast[tid];
    __syncthreads();

    const int warp = tid >> 5;
    const int lane = tid & 31;
    const int row = blockIdx.x * 8 + warp;
    const float* hrow = g_h + (size_t)row * H_DIM;

    float acc[D_OUT] = {};
    #pragma unroll 4
    for (int t = 0; t < H_DIM / 32; t++) {
        int k = t * 32 + lane;
        float xv = tanhf((hrow[k] - mush[k]) * rsh[k]);
        #pragma unroll
        for (int c = 0; c < D_OUT; c++) acc[c] = fmaf(xv, msh[c][k], acc[c]);
    }
    #pragma unroll
    for (int c = 0; c < D_OUT; c++)
        #pragma unroll
        for (int o = 16; o; o >>= 1) acc[c] += __shfl_xor_sync(0xFFFFFFFFu, acc[c], o);

    if (lane == 0) {
        float lg[D_OUT];
        float mx = -1e30f;
        #pragma unroll
        for (int c = 0; c < D_OUT; c++) { lg[c] = acc[c] + th[c]; mx = fmaxf(mx, lg[c]); }
        float se = 0.f;
        #pragma unroll
        for (int c = 0; c < D_OUT; c++) se += expf(lg[c] - mx);
        float lse = mx + logf(se);
        int am = 0; float bm = lg[0];
        #pragma unroll
        for (int c = 1; c < D_OUT; c++) if (lg[c] > bm) { bm = lg[c]; am = c; }
        #pragma unroll
        for (int c = 0; c < D_OUT; c++) {
            out_h[(size_t)row * D_OUT + c]  = lg[c];
            out_lp[(size_t)row * D_OUT + c] = lg[c] - lse;
        }
        int tgt = target[row];
        wloss[warp] = -(lg[tgt] - lse);
        wcorr[warp] = (am == tgt) ? 1 : 0;
    }
    __syncthreads();
    if (tid == 0) {
        float ls = 0.f; int cc = 0;
        #pragma unroll
        for (int w = 0; w < 8; w++) { ls += wloss[w]; cc += wcorr[w]; }
        atomicAdd(&g_loss[0], ls);
        atomicAdd(&g_correct[0], cc);
    }
}
__global__ void k_finalize_out(float* __restrict__ out_tail) {
    const float inv = 1.0f / (float)M_ROWS;
    out_tail[0] = g_loss[0] * inv;
    out_tail[1] = (float)g_correct[0] * inv;
}

// ---------------------------------------------------------------------------
extern "C" void kernel_launch(void* const* d_in, const int* in_sizes, int n_in,
                              void* d_out, int out_size)
{
    (void)in_sizes; (void)n_in; (void)out_size;
    const float* x      = (const float*)d_in[0];
    const int*   target = (const int*)d_in[1];
    const float* w0     = (const float*)d_in[2];
    const float* w1     = (const float*)d_in[3];
    const float* w3     = (const float*)d_in[5];
    const float* wlast  = (const float*)d_in[6];
    const float* th0    = (const float*)d_in[7];
    const float* th1    = (const float*)d_in[8];
    const float* thlast = (const float*)d_in[10];
    float* out = (float*)d_out;

    cudaFuncSetAttribute(k_gemm1, cudaFuncAttributeMaxDynamicSharedMemorySize, SMEM_TOTAL);
    cudaFuncSetAttribute(k_gemm2, cudaFuncAttributeMaxDynamicSharedMemorySize, SMEM_TOTAL);
    cudaFuncSetAttribute(k_gemm3, cudaFuncAttributeMaxDynamicSharedMemorySize, SMEM_TOTAL);

    dim3 g2(H_DIM / 128, M_ROWS / 128);

    // launch order keeps gemm1 at index 3 (the launch ncu captures)
    k_prep_w0<<<H_DIM, 256>>>(w0);                       // 0
    k_split_x<<<2048, 256>>>(x);                         // 1
    k_prep_misc<<<20, 256>>>(w0, wlast);                 // 2

    k_gemm1<<<g2, 256, SMEM_TOTAL>>>(th0);               // 3  <- profiled

    k_prep_w13<<<H_DIM, 256>>>(w1, w3);                  // 4
    k_diag_rows<<<128, 256>>>(w1, w3);                   // 5
    k_split_act<0><<<2048, 256>>>();                     // 6 (stats0 inline)

    k_gemm2<<<g2, 256, SMEM_TOTAL>>>(th1);               // 7
    k_split_act<1><<<2048, 256>>>();                     // 8 (stats1 inline)

    k_gemm3<<<g2, 256, SMEM_TOTAL>>>(th1);               // 9 (th1 reused, faithful)

    float* out_h  = out;
    float* out_lp = out + (size_t)M_ROWS * D_OUT;
    float* out_tl = out + (size_t)2 * M_ROWS * D_OUT;
    k_last<<<M_ROWS / 8, 256>>>(thlast, target, out_h, out_lp); // 10 (stats2 inline)
    k_finalize_out<<<1, 1>>>(out_tl);                           // 11
}